// round 2
// baseline (speedup 1.0000x reference)
#include <cuda_runtime.h>
#include <math.h>

// Problem constants
#define BB  8
#define SS  1024
#define DD  768
#define EE  24
#define DHH 128
#define DFF 384
#define NN  6144          // S*H tokens per batch
#define KK  1024          // tokens per expert

// ---------------- scratch (device globals; no allocation allowed) -----------
__device__ float g_x1[(size_t)BB * NN * DHH];     // head-projected tokens [B][N][DH]
__device__ float g_gates[(size_t)BB * EE * NN];   // softmax gates [B][E][N]
__device__ int   g_idx[(size_t)BB * EE * KK];     // selected token index
__device__ float g_gateval[(size_t)BB * EE * KK]; // selected gate value
__device__ float g_xout[(size_t)BB * NN * DHH];   // scatter accumulator

// ---------------- generic 128x128x8 fp32 SGEMM: C = A(MxK) @ B(KxN) ---------
__global__ __launch_bounds__(256) void sgemm128(const float* __restrict__ A,
                                                const float* __restrict__ B,
                                                float* __restrict__ C,
                                                int M, int N, int K) {
    __shared__ float As[8][128];
    __shared__ float Bs[8][128];
    const int tid = threadIdx.x;
    const int bx = blockIdx.x, by = blockIdx.y;
    const int aRow = tid >> 1;
    const int aCol = (tid & 1) << 2;
    const int bRow = tid >> 5;
    const int bCol = (tid & 31) << 2;
    const int tr = (tid >> 4) << 3;
    const int tc = (tid & 15) << 3;

    const float* Ap = A + (size_t)(by * 128 + aRow) * K + aCol;
    const float* Bp = B + (size_t)bRow * N + bx * 128 + bCol;

    float acc[8][8];
#pragma unroll
    for (int i = 0; i < 8; i++)
#pragma unroll
        for (int j = 0; j < 8; j++) acc[i][j] = 0.f;

    for (int k0 = 0; k0 < K; k0 += 8) {
        float4 av = *(const float4*)(Ap + k0);
        As[aCol + 0][aRow] = av.x;
        As[aCol + 1][aRow] = av.y;
        As[aCol + 2][aRow] = av.z;
        As[aCol + 3][aRow] = av.w;
        *(float4*)&Bs[bRow][bCol] = *(const float4*)(Bp + (size_t)k0 * N);
        __syncthreads();
#pragma unroll
        for (int k = 0; k < 8; k++) {
            float ar[8], br[8];
            *(float4*)&ar[0] = *(const float4*)&As[k][tr];
            *(float4*)&ar[4] = *(const float4*)&As[k][tr + 4];
            *(float4*)&br[0] = *(const float4*)&Bs[k][tc];
            *(float4*)&br[4] = *(const float4*)&Bs[k][tc + 4];
#pragma unroll
            for (int i = 0; i < 8; i++)
#pragma unroll
                for (int j = 0; j < 8; j++) acc[i][j] += ar[i] * br[j];
        }
        __syncthreads();
    }
    float* Cp = C + (size_t)(by * 128 + tr) * N + bx * 128 + tc;
#pragma unroll
    for (int i = 0; i < 8; i++) {
        *(float4*)(Cp + (size_t)i * N)     = make_float4(acc[i][0], acc[i][1], acc[i][2], acc[i][3]);
        *(float4*)(Cp + (size_t)i * N + 4) = make_float4(acc[i][4], acc[i][5], acc[i][6], acc[i][7]);
    }
}

// ---------------- gating: logits = x1 . choice^T ; softmax over E -----------
// one warp per token, 8 warps per block
__global__ __launch_bounds__(256) void gating_kernel(const float* __restrict__ choice) {
    __shared__ float cs[EE * DHH];
    for (int i = threadIdx.x; i < EE * DHH; i += 256) cs[i] = choice[i];
    __syncthreads();

    const int warp = threadIdx.x >> 5;
    const int lane = threadIdx.x & 31;
    const long token = (long)blockIdx.x * 8 + warp;   // 0 .. B*N-1
    if (token >= (long)BB * NN) return;

    const float* xr = g_x1 + token * DHH;
    float4 xv = ((const float4*)xr)[lane];

    float l[EE];
#pragma unroll
    for (int e = 0; e < EE; e++) {
        float4 cv = ((const float4*)(cs + e * DHH))[lane];
        float p = xv.x * cv.x + xv.y * cv.y + xv.z * cv.z + xv.w * cv.w;
#pragma unroll
        for (int o = 16; o > 0; o >>= 1) p += __shfl_xor_sync(0xffffffffu, p, o);
        l[e] = p;
    }
    float m = l[0];
#pragma unroll
    for (int e = 1; e < EE; e++) m = fmaxf(m, l[e]);
    float s = 0.f;
#pragma unroll
    for (int e = 0; e < EE; e++) { l[e] = expf(l[e] - m); s += l[e]; }
    const float inv = 1.f / s;
    const int b = (int)(token / NN);
    const int n = (int)(token % NN);
    if (lane < EE)
        g_gates[((size_t)b * EE + lane) * NN + n] = l[lane] * inv;
}

// ---------------- deterministic top-K per (b,e) via radix select ------------
// K-th largest threshold over positive floats (uint-order monotone), then
// ordered compaction: all strictly-greater tokens, plus lowest-index ties —
// matches jax.lax.top_k's stable descending selection set.
__global__ __launch_bounds__(256) void topk_kernel() {
    __shared__ unsigned sv[NN];        // 24 KB
    __shared__ int red[256];
    __shared__ int cnts[256];
    __shared__ int gtoff[256];
    __shared__ int eqoff[256];
    __shared__ int tot_gt;

    const int be = blockIdx.x;         // b*EE + e
    const int tid = threadIdx.x;
    const float* g = g_gates + (size_t)be * NN;
    for (int i = tid; i < NN; i += 256) sv[i] = __float_as_uint(g[i]);
    __syncthreads();

    unsigned thr = 0u;
    for (int bit = 30; bit >= 0; bit--) {
        unsigned cand = thr | (1u << bit);
        int c = 0;
        for (int i = tid; i < NN; i += 256) c += (sv[i] >= cand) ? 1 : 0;
        red[tid] = c;
        __syncthreads();
        for (int s = 128; s > 0; s >>= 1) {
            if (tid < s) red[tid] += red[tid + s];
            __syncthreads();
        }
        int tot = red[0];
        __syncthreads();
        if (tot >= KK) thr = cand;
    }

    // per-thread contiguous chunk of 24 indices -> ordered, deterministic
    const int base = tid * (NN / 256);
    int lgt = 0, leq = 0;
#pragma unroll
    for (int j = 0; j < NN / 256; j++) {
        unsigned v = sv[base + j];
        lgt += (v > thr);
        leq += (v == thr);
    }
    red[tid] = lgt;
    cnts[tid] = leq;
    __syncthreads();
    if (tid == 0) {
        int a = 0;
        for (int i = 0; i < 256; i++) { gtoff[i] = a; a += red[i]; }
        tot_gt = a;
        a = 0;
        for (int i = 0; i < 256; i++) { eqoff[i] = a; a += cnts[i]; }
    }
    __syncthreads();

    const int ngt = tot_gt;
    int pgt = gtoff[tid];
    int peq = ngt + eqoff[tid];
    int*   ip = g_idx     + (size_t)be * KK;
    float* gp = g_gateval + (size_t)be * KK;
#pragma unroll
    for (int j = 0; j < NN / 256; j++) {
        unsigned v = sv[base + j];
        if (v > thr) {
            ip[pgt] = base + j;
            gp[pgt] = __uint_as_float(v);
            pgt++;
        } else if (v == thr) {
            if (peq < KK) {
                ip[peq] = base + j;
                gp[peq] = __uint_as_float(v);
            }
            peq++;
        }
    }
}

// ---------------- zero accumulator ------------------------------------------
__global__ void zero_kernel() {
    size_t i = ((size_t)blockIdx.x * blockDim.x + threadIdx.x) * 4;
    if (i < (size_t)BB * NN * DHH) {
        *(float4*)(g_xout + i) = make_float4(0.f, 0.f, 0.f, 0.f);
    }
}

// ---------------- fused gather -> FFN -> gated scatter ----------------------
// block = (token_tile of 128, expert e, batch b); 256 threads
// smem: XsT[k][m] 128x132, HsT[df][m] 128x132, Ws[16][128], Gs[128]
#define XS_STRIDE 132
#define FFN_SMEM_FLOATS (2 * 128 * XS_STRIDE + 16 * 128 + 128)
#define FFN_SMEM_BYTES (FFN_SMEM_FLOATS * 4)

__global__ __launch_bounds__(256, 1) void ffn_kernel(const float* __restrict__ w1,
                                                     const float* __restrict__ w2) {
    extern __shared__ float sm[];
    float* XsT = sm;                         // [128][132]  (X transposed: [k][m])
    float* HsT = sm + 128 * XS_STRIDE;       // [128][132]  (H transposed: [df][m])
    float* Ws  = sm + 2 * 128 * XS_STRIDE;   // [16][128]
    float* Gs  = Ws + 16 * 128;              // [128]

    const int tile = blockIdx.x;             // 0..7
    const int e    = blockIdx.y;
    const int b    = blockIdx.z;
    const int tid  = threadIdx.x;
    const int be   = b * EE + e;

    const int*   idxp = g_idx     + (size_t)be * KK + tile * 128;
    const float* gvp  = g_gateval + (size_t)be * KK + tile * 128;

    // gather tokens into XsT (transposed)
    {
        const int m = tid >> 1;
        const int half = tid & 1;
        const int tok = idxp[m];
        const float* xr = g_x1 + ((size_t)b * NN + tok) * DHH + half * 64;
#pragma unroll
        for (int j = 0; j < 64; j += 4) {
            float4 v = *(const float4*)(xr + j);
            int c = half * 64 + j;
            XsT[(c + 0) * XS_STRIDE + m] = v.x;
            XsT[(c + 1) * XS_STRIDE + m] = v.y;
            XsT[(c + 2) * XS_STRIDE + m] = v.z;
            XsT[(c + 3) * XS_STRIDE + m] = v.w;
        }
        if (tid < 128) Gs[tid] = gvp[tid];
    }
    __syncthreads();

    const int tr = (tid >> 4) << 3;
    const int tc = (tid & 15) << 3;
    const int wr = tid >> 5;
    const int wc = (tid & 31) << 2;

    float yacc[8][8];
#pragma unroll
    for (int i = 0; i < 8; i++)
#pragma unroll
        for (int j = 0; j < 8; j++) yacc[i][j] = 0.f;

    const float* w1e = w1 + (size_t)e * DHH * DFF;
    const float* w2e = w2 + (size_t)e * DFF * DHH;

    for (int c = 0; c < 3; c++) {
        float hacc[8][8];
#pragma unroll
        for (int i = 0; i < 8; i++)
#pragma unroll
            for (int j = 0; j < 8; j++) hacc[i][j] = 0.f;

        // H_chunk = X @ w1[:, c*128:(c+1)*128]
        for (int k0 = 0; k0 < 128; k0 += 16) {
#pragma unroll
            for (int r = 0; r < 16; r += 8) {
                *(float4*)(Ws + (wr + r) * 128 + wc) =
                    *(const float4*)(w1e + (size_t)(k0 + wr + r) * DFF + c * 128 + wc);
            }
            __syncthreads();
#pragma unroll
            for (int kk = 0; kk < 16; kk++) {
                float ar[8], br[8];
                *(float4*)&ar[0] = *(const float4*)&XsT[(k0 + kk) * XS_STRIDE + tr];
                *(float4*)&ar[4] = *(const float4*)&XsT[(k0 + kk) * XS_STRIDE + tr + 4];
                *(float4*)&br[0] = *(const float4*)&Ws[kk * 128 + tc];
                *(float4*)&br[4] = *(const float4*)&Ws[kk * 128 + tc + 4];
#pragma unroll
                for (int i = 0; i < 8; i++)
#pragma unroll
                    for (int j = 0; j < 8; j++) hacc[i][j] += ar[i] * br[j];
            }
            __syncthreads();
        }
        // silu + store transposed into HsT
#pragma unroll
        for (int i = 0; i < 8; i++)
#pragma unroll
            for (int j = 0; j < 8; j++) {
                float v = hacc[i][j];
                v = v / (1.f + expf(-v));
                HsT[(tc + j) * XS_STRIDE + (tr + i)] = v;
            }
        __syncthreads();

        // Y += H_chunk @ w2[c*128:(c+1)*128, :]
        for (int k0 = 0; k0 < 128; k0 += 16) {
#pragma unroll
            for (int r = 0; r < 16; r += 8) {
                *(float4*)(Ws + (wr + r) * 128 + wc) =
                    *(const float4*)(w2e + (size_t)(c * 128 + k0 + wr + r) * DHH + wc);
            }
            __syncthreads();
#pragma unroll
            for (int kk = 0; kk < 16; kk++) {
                float ar[8], br[8];
                *(float4*)&ar[0] = *(const float4*)&HsT[(k0 + kk) * XS_STRIDE + tr];
                *(float4*)&ar[4] = *(const float4*)&HsT[(k0 + kk) * XS_STRIDE + tr + 4];
                *(float4*)&br[0] = *(const float4*)&Ws[kk * 128 + tc];
                *(float4*)&br[4] = *(const float4*)&Ws[kk * 128 + tc + 4];
#pragma unroll
                for (int i = 0; i < 8; i++)
#pragma unroll
                    for (int j = 0; j < 8; j++) yacc[i][j] += ar[i] * br[j];
            }
            __syncthreads();
        }
    }

    // gated scatter-add
#pragma unroll
    for (int i = 0; i < 8; i++) {
        const int m = tr + i;
        const int tok = idxp[m];
        const float gv = Gs[m];
        float* outp = g_xout + ((size_t)b * NN + tok) * DHH + tc;
#pragma unroll
        for (int j = 0; j < 8; j++) atomicAdd(outp + j, yacc[i][j] * gv);
    }
}

// ---------------- launch ----------------------------------------------------
extern "C" void kernel_launch(void* const* d_in, const int* in_sizes, int n_in,
                              void* d_out, int out_size) {
    const float* x      = (const float*)d_in[0];
    const float* choice = (const float*)d_in[1];
    const float* w1     = (const float*)d_in[2];
    const float* w2     = (const float*)d_in[3];
    const float* head   = (const float*)d_in[4];
    const float* merge  = (const float*)d_in[5];
    float* out = (float*)d_out;

    float *x1p = nullptr, *xop = nullptr;
    cudaGetSymbolAddress((void**)&x1p, g_x1);
    cudaGetSymbolAddress((void**)&xop, g_xout);

    // 1) head projection: [8192,768] @ [768,768]
    dim3 gproj(DD / 128, (BB * SS) / 128);
    sgemm128<<<gproj, 256>>>(x, head, x1p, BB * SS, DD, DD);

    // 2) gating + softmax
    gating_kernel<<<(BB * NN) / 8, 256>>>(choice);

    // 3) per-(b,e) top-K
    topk_kernel<<<BB * EE, 256>>>();

    // 4) zero accumulator
    zero_kernel<<<(BB * NN * DHH) / (256 * 4), 256>>>();

    // 5) fused gather -> FFN -> gated scatter
    cudaFuncSetAttribute(ffn_kernel, cudaFuncAttributeMaxDynamicSharedMemorySize,
                         FFN_SMEM_BYTES);
    dim3 gffn(KK / 128, EE, BB);
    ffn_kernel<<<gffn, 256, FFN_SMEM_BYTES>>>(w1, w2);

    // 6) merge projection
    sgemm128<<<gproj, 256>>>(xop, merge, out, BB * SS, DD, DD);
}

// round 5
// speedup vs baseline: 1.3673x; 1.3673x over previous
#include <cuda_runtime.h>
#include <math.h>
#include <stdint.h>

// Problem constants
#define BB  8
#define SS  1024
#define DD  768
#define EE  24
#define DHH 128
#define DFF 384
#define NN  6144          // S*H tokens per batch
#define KK  1024          // tokens per expert

// ---------------- scratch (device globals; no allocation allowed) -----------
__device__ float g_x1[(size_t)BB * NN * DHH];     // head-projected tokens (fp32, accurate)
__device__ float g_gates[(size_t)BB * EE * NN];
__device__ int   g_idx[(size_t)BB * EE * KK];
__device__ float g_gateval[(size_t)BB * EE * KK];
__device__ float g_xout[(size_t)BB * NN * DHH];   // scatter accumulator (fp32)

__device__ float g_xh[(size_t)BB * SS * DD];      // x split hi/lo (tf32)
__device__ float g_xl[(size_t)BB * SS * DD];
__device__ float g_hh[DD * DD];                   // head split
__device__ float g_hl[DD * DD];
__device__ float g_mh[DD * DD];                   // merge split
__device__ float g_ml[DD * DD];
__device__ float g_w1r[(size_t)EE * DHH * DFF];   // w1 rounded to tf32
__device__ float g_w2r[(size_t)EE * DFF * DHH];   // w2 rounded to tf32
__device__ float g_xoh[(size_t)BB * NN * DHH];    // xout split hi/lo
__device__ float g_xol[(size_t)BB * NN * DHH];

// ---------------- helpers ----------------------------------------------------
__device__ __forceinline__ float f_rna(float x) {
    uint32_t u;
    asm("cvt.rna.tf32.f32 %0, %1;" : "=r"(u) : "f"(x));
    return __uint_as_float(u);
}

__device__ __forceinline__ void mma8(float* c, const uint32_t* a, const uint32_t* b) {
    asm volatile(
        "mma.sync.aligned.m16n8k8.row.col.f32.tf32.tf32.f32 "
        "{%0,%1,%2,%3}, {%4,%5,%6,%7}, {%8,%9}, {%0,%1,%2,%3};\n"
        : "+f"(c[0]), "+f"(c[1]), "+f"(c[2]), "+f"(c[3])
        : "r"(a[0]), "r"(a[1]), "r"(a[2]), "r"(a[3]), "r"(b[0]), "r"(b[1]));
}

__device__ __forceinline__ void cp16(void* smem, const void* g) {
    uint32_t s = (uint32_t)__cvta_generic_to_shared(smem);
    asm volatile("cp.async.ca.shared.global [%0], [%1], 16;" :: "r"(s), "l"(g));
}
#define CP_COMMIT asm volatile("cp.async.commit_group;")
#define CP_WAIT0  asm volatile("cp.async.wait_group 0;")
#define CP_WAIT1  asm volatile("cp.async.wait_group 1;")

// ---------------- elementwise tf32 split / round -----------------------------
__global__ void split_tf32_kernel(const float* __restrict__ src,
                                  float* __restrict__ hi, float* __restrict__ lo,
                                  size_t n) {
    size_t i = ((size_t)blockIdx.x * blockDim.x + threadIdx.x) * 4;
    if (i >= n) return;
    float4 v = *(const float4*)(src + i);
    float4 h, l;
    h.x = f_rna(v.x); l.x = f_rna(v.x - h.x);
    h.y = f_rna(v.y); l.y = f_rna(v.y - h.y);
    h.z = f_rna(v.z); l.z = f_rna(v.z - h.z);
    h.w = f_rna(v.w); l.w = f_rna(v.w - h.w);
    *(float4*)(hi + i) = h;
    *(float4*)(lo + i) = l;
}

__global__ void round_tf32_kernel(const float* __restrict__ src,
                                  float* __restrict__ dst, size_t n) {
    size_t i = ((size_t)blockIdx.x * blockDim.x + threadIdx.x) * 4;
    if (i >= n) return;
    float4 v = *(const float4*)(src + i);
    v.x = f_rna(v.x); v.y = f_rna(v.y); v.z = f_rna(v.z); v.w = f_rna(v.w);
    *(float4*)(dst + i) = v;
}

// ---------------- 3xTF32 GEMM: C = A@B (A[M,K], B[K,N] row-major) ------------
// block 128x128, 8 warps (warp 64x32), K-tile 32, cp.async double buffer.
#define SA 36      // A smem row stride (== 4 mod 32 -> conflict-free a-frags)
#define SB 136     // B smem row stride (== 8 mod 32 -> conflict-free b-frags)
#define G3_A  (128 * SA)            // 4608
#define G3_B  (32 * SB)             // 4352
#define G3_BUF (2 * G3_A + 2 * G3_B)  // 17920 floats per buffer
#define G3_SMEM_BYTES (2 * G3_BUF * 4)

__global__ __launch_bounds__(256) void gemm3x_kernel(
    const float* __restrict__ Ah, const float* __restrict__ Al,
    const float* __restrict__ Bh, const float* __restrict__ Bl,
    float* __restrict__ C, int M, int N, int K)
{
    extern __shared__ float sm[];
    const int tid = threadIdx.x;
    const int bm = blockIdx.y * 128, bn = blockIdx.x * 128;

    const int ar = tid & 127, aseg = tid >> 7;   // A staging: row, 16-float seg
    const int br = tid & 31,  bseg = tid >> 5;   // B staging: row, 16-float seg

    const int warp = tid >> 5, lane = tid & 31;
    const int wm = (warp >> 2) * 64, wn = (warp & 3) * 32;
    const int ly = lane >> 2, lx = lane & 3;

    const int T = K / 32;

    auto stage = [&](int buf, int kt) {
        float* base = sm + buf * G3_BUF;
        float* ahd = base + ar * SA + aseg * 16;
        float* ald = base + G3_A + ar * SA + aseg * 16;
        const float* ahs = Ah + (size_t)(bm + ar) * K + kt * 32 + aseg * 16;
        const float* als = Al + (size_t)(bm + ar) * K + kt * 32 + aseg * 16;
#pragma unroll
        for (int j = 0; j < 16; j += 4) { cp16(ahd + j, ahs + j); cp16(ald + j, als + j); }
        float* bhd = base + 2 * G3_A + br * SB + bseg * 16;
        float* bld = base + 2 * G3_A + G3_B + br * SB + bseg * 16;
        const float* bhs = Bh + (size_t)(kt * 32 + br) * N + bn + bseg * 16;
        const float* bls = Bl + (size_t)(kt * 32 + br) * N + bn + bseg * 16;
#pragma unroll
        for (int j = 0; j < 16; j += 4) { cp16(bhd + j, bhs + j); cp16(bld + j, bls + j); }
    };

    float c[4][4][4];
#pragma unroll
    for (int i = 0; i < 4; i++)
#pragma unroll
        for (int j = 0; j < 4; j++)
#pragma unroll
            for (int k = 0; k < 4; k++) c[i][j][k] = 0.f;

    stage(0, 0);
    CP_COMMIT;

    for (int t = 0; t < T; t++) {
        if (t + 1 < T) { stage((t + 1) & 1, t + 1); CP_COMMIT; CP_WAIT1; }
        else           { CP_WAIT0; }
        __syncthreads();
        const float* base = sm + (t & 1) * G3_BUF;
        const float* Ash = base;
        const float* Asl = base + G3_A;
        const float* Bsh = base + 2 * G3_A;
        const float* Bsl = base + 2 * G3_A + G3_B;
#pragma unroll
        for (int ks = 0; ks < 4; ks++) {
            const int k0 = ks * 8;
            uint32_t ah[4][4], al[4][4], bh[4][2], bl[4][2];
#pragma unroll
            for (int am = 0; am < 4; am++) {
                const int off = (wm + am * 16 + ly) * SA + k0 + lx;
                ah[am][0] = __float_as_uint(Ash[off]);
                ah[am][1] = __float_as_uint(Ash[off + 8 * SA]);
                ah[am][2] = __float_as_uint(Ash[off + 4]);
                ah[am][3] = __float_as_uint(Ash[off + 8 * SA + 4]);
                al[am][0] = __float_as_uint(Asl[off]);
                al[am][1] = __float_as_uint(Asl[off + 8 * SA]);
                al[am][2] = __float_as_uint(Asl[off + 4]);
                al[am][3] = __float_as_uint(Asl[off + 8 * SA + 4]);
            }
#pragma unroll
            for (int an = 0; an < 4; an++) {
                const int off = (k0 + lx) * SB + wn + an * 8 + ly;
                bh[an][0] = __float_as_uint(Bsh[off]);
                bh[an][1] = __float_as_uint(Bsh[off + 4 * SB]);
                bl[an][0] = __float_as_uint(Bsl[off]);
                bl[an][1] = __float_as_uint(Bsl[off + 4 * SB]);
            }
#pragma unroll
            for (int am = 0; am < 4; am++)
#pragma unroll
                for (int an = 0; an < 4; an++) {
                    mma8(c[am][an], ah[am], bh[an]);
                    mma8(c[am][an], ah[am], bl[an]);
                    mma8(c[am][an], al[am], bh[an]);
                }
        }
        __syncthreads();
    }

#pragma unroll
    for (int am = 0; am < 4; am++) {
        const int row = bm + wm + am * 16 + ly;
#pragma unroll
        for (int an = 0; an < 4; an++) {
            const int col = bn + wn + an * 8 + 2 * lx;
            *(float2*)(C + (size_t)row * N + col)       = make_float2(c[am][an][0], c[am][an][1]);
            *(float2*)(C + (size_t)(row + 8) * N + col) = make_float2(c[am][an][2], c[am][an][3]);
        }
    }
}

// ---------------- gating: logits = x1 . choice^T ; softmax over E -----------
__global__ __launch_bounds__(256) void gating_kernel(const float* __restrict__ choice) {
    __shared__ float cs[EE * DHH];
    for (int i = threadIdx.x; i < EE * DHH; i += 256) cs[i] = choice[i];
    __syncthreads();

    const int warp = threadIdx.x >> 5;
    const int lane = threadIdx.x & 31;
    const long token = (long)blockIdx.x * 8 + warp;
    if (token >= (long)BB * NN) return;

    const float* xr = g_x1 + token * DHH;
    float4 xv = ((const float4*)xr)[lane];

    float l[EE];
#pragma unroll
    for (int e = 0; e < EE; e++) {
        float4 cv = ((const float4*)(cs + e * DHH))[lane];
        float p = xv.x * cv.x + xv.y * cv.y + xv.z * cv.z + xv.w * cv.w;
#pragma unroll
        for (int o = 16; o > 0; o >>= 1) p += __shfl_xor_sync(0xffffffffu, p, o);
        l[e] = p;
    }
    float m = l[0];
#pragma unroll
    for (int e = 1; e < EE; e++) m = fmaxf(m, l[e]);
    float s = 0.f;
#pragma unroll
    for (int e = 0; e < EE; e++) { l[e] = expf(l[e] - m); s += l[e]; }
    const float inv = 1.f / s;
    const int b = (int)(token / NN);
    const int n = (int)(token % NN);
    if (lane < EE)
        g_gates[((size_t)b * EE + lane) * NN + n] = l[lane] * inv;
}

// ---------------- deterministic top-K per (b,e) via radix select ------------
__global__ __launch_bounds__(256) void topk_kernel() {
    __shared__ unsigned sv[NN];
    __shared__ int red[256];
    __shared__ int cnts[256];
    __shared__ int gtoff[256];
    __shared__ int eqoff[256];
    __shared__ int tot_gt;

    const int be = blockIdx.x;
    const int tid = threadIdx.x;
    const float* g = g_gates + (size_t)be * NN;
    for (int i = tid; i < NN; i += 256) sv[i] = __float_as_uint(g[i]);
    __syncthreads();

    unsigned thr = 0u;
    for (int bit = 30; bit >= 0; bit--) {
        unsigned cand = thr | (1u << bit);
        int c = 0;
        for (int i = tid; i < NN; i += 256) c += (sv[i] >= cand) ? 1 : 0;
        red[tid] = c;
        __syncthreads();
        for (int s = 128; s > 0; s >>= 1) {
            if (tid < s) red[tid] += red[tid + s];
            __syncthreads();
        }
        int tot = red[0];
        __syncthreads();
        if (tot >= KK) thr = cand;
    }

    const int base = tid * (NN / 256);
    int lgt = 0, leq = 0;
#pragma unroll
    for (int j = 0; j < NN / 256; j++) {
        unsigned v = sv[base + j];
        lgt += (v > thr);
        leq += (v == thr);
    }
    red[tid] = lgt;
    cnts[tid] = leq;
    __syncthreads();
    if (tid == 0) {
        int a = 0;
        for (int i = 0; i < 256; i++) { gtoff[i] = a; a += red[i]; }
        tot_gt = a;
        a = 0;
        for (int i = 0; i < 256; i++) { eqoff[i] = a; a += cnts[i]; }
    }
    __syncthreads();

    const int ngt = tot_gt;
    int pgt = gtoff[tid];
    int peq = ngt + eqoff[tid];
    int*   ip = g_idx     + (size_t)be * KK;
    float* gp = g_gateval + (size_t)be * KK;
#pragma unroll
    for (int j = 0; j < NN / 256; j++) {
        unsigned v = sv[base + j];
        if (v > thr) {
            ip[pgt] = base + j;
            gp[pgt] = __uint_as_float(v);
            pgt++;
        } else if (v == thr) {
            if (peq < KK) {
                ip[peq] = base + j;
                gp[peq] = __uint_as_float(v);
            }
            peq++;
        }
    }
}

// ---------------- zero accumulator ------------------------------------------
__global__ void zero_kernel() {
    size_t i = ((size_t)blockIdx.x * blockDim.x + threadIdx.x) * 4;
    if (i < (size_t)BB * NN * DHH) {
        *(float4*)(g_xout + i) = make_float4(0.f, 0.f, 0.f, 0.f);
    }
}

// ---------------- fused gather -> FFN (tf32 mma) -> gated scatter ------------
// block = (token_tile 128, expert, batch), 256 threads, 8 warps (warp 64x32).
#define FS_X 132   // X/H smem stride (== 4 mod 32)
#define FS_W 136   // W smem stride  (== 8 mod 32)
#define FFN_XS   (128 * FS_X)              // 16896
#define FFN_WS   (128 * FS_W)              // 17408
#define FFN_SMEM_FLOATS (2 * FFN_XS + FFN_WS + 256)
#define FFN_SMEM_BYTES (FFN_SMEM_FLOATS * 4)

__global__ __launch_bounds__(256, 1) void ffn_tf32_kernel(const float* __restrict__ w1r,
                                                          const float* __restrict__ w2r) {
    extern __shared__ float sm[];
    float* Xs = sm;
    float* Hs = sm + FFN_XS;
    float* Ws = sm + 2 * FFN_XS;
    int*   toks = (int*)(sm + 2 * FFN_XS + FFN_WS);
    float* Gs   = sm + 2 * FFN_XS + FFN_WS + 128;

    const int tile = blockIdx.x, e = blockIdx.y, b = blockIdx.z;
    const int tid = threadIdx.x;
    const int be = b * EE + e;
    const int* idxp = g_idx + (size_t)be * KK + tile * 128;
    const float* gvp = g_gateval + (size_t)be * KK + tile * 128;
    const float* w1e = w1r + (size_t)e * DHH * DFF;
    const float* w2e = w2r + (size_t)e * DFF * DHH;

    const int row = tid & 127, seg = tid >> 7;

    // prologue: issue async load of w1 chunk 0
    {
        float* wd = Ws + row * FS_W + seg * 64;
        const float* wsrc = w1e + (size_t)row * DFF + seg * 64;
#pragma unroll
        for (int j = 0; j < 64; j += 4) cp16(wd + j, wsrc + j);
    }
    CP_COMMIT;

    // gather X (convert to tf32 while staging)
    {
        const int tok = idxp[row];
        if (seg == 0) { toks[row] = tok; Gs[row] = gvp[row]; }
        const float* xr = g_x1 + ((size_t)b * NN + tok) * DHH + seg * 64;
        float* xd = Xs + row * FS_X + seg * 64;
#pragma unroll
        for (int j = 0; j < 64; j += 4) {
            float4 v = *(const float4*)(xr + j);
            xd[j]     = f_rna(v.x);
            xd[j + 1] = f_rna(v.y);
            xd[j + 2] = f_rna(v.z);
            xd[j + 3] = f_rna(v.w);
        }
    }

    const int warp = tid >> 5, lane = tid & 31;
    const int wm = (warp >> 2) * 64, wn = (warp & 3) * 32;
    const int ly = lane >> 2, lx = lane & 3;

    float yacc[4][4][4];
#pragma unroll
    for (int i = 0; i < 4; i++)
#pragma unroll
        for (int j = 0; j < 4; j++)
#pragma unroll
            for (int k = 0; k < 4; k++) yacc[i][j][k] = 0.f;

    for (int c = 0; c < 3; c++) {
        CP_WAIT0;
        __syncthreads();

        // H = Xs @ w1_chunk
        float h[4][4][4];
#pragma unroll
        for (int i = 0; i < 4; i++)
#pragma unroll
            for (int j = 0; j < 4; j++)
#pragma unroll
                for (int k = 0; k < 4; k++) h[i][j][k] = 0.f;

#pragma unroll 4
        for (int ks = 0; ks < 16; ks++) {
            const int k0 = ks * 8;
            uint32_t a[4][4], bf[4][2];
#pragma unroll
            for (int am = 0; am < 4; am++) {
                const int off = (wm + am * 16 + ly) * FS_X + k0 + lx;
                a[am][0] = __float_as_uint(Xs[off]);
                a[am][1] = __float_as_uint(Xs[off + 8 * FS_X]);
                a[am][2] = __float_as_uint(Xs[off + 4]);
                a[am][3] = __float_as_uint(Xs[off + 8 * FS_X + 4]);
            }
#pragma unroll
            for (int an = 0; an < 4; an++) {
                const int off = (k0 + lx) * FS_W + wn + an * 8 + ly;
                bf[an][0] = __float_as_uint(Ws[off]);
                bf[an][1] = __float_as_uint(Ws[off + 4 * FS_W]);
            }
#pragma unroll
            for (int am = 0; am < 4; am++)
#pragma unroll
                for (int an = 0; an < 4; an++) mma8(h[am][an], a[am], bf[an]);
        }
        __syncthreads();   // done reading w1 chunk

        // issue async load of w2 chunk c (overlaps silu below)
        {
            float* wd = Ws + row * FS_W + seg * 64;
            const float* wsrc = w2e + (size_t)(c * 128 + row) * DHH + seg * 64;
#pragma unroll
            for (int j = 0; j < 64; j += 4) cp16(wd + j, wsrc + j);
        }
        CP_COMMIT;

        // silu -> Hs (tf32-rounded)
#pragma unroll
        for (int am = 0; am < 4; am++) {
            const int r0 = wm + am * 16 + ly;
#pragma unroll
            for (int an = 0; an < 4; an++) {
                const int col = wn + an * 8 + 2 * lx;
                float v0 = h[am][an][0], v1 = h[am][an][1];
                float v2 = h[am][an][2], v3 = h[am][an][3];
                v0 = v0 / (1.f + expf(-v0));
                v1 = v1 / (1.f + expf(-v1));
                v2 = v2 / (1.f + expf(-v2));
                v3 = v3 / (1.f + expf(-v3));
                *(float2*)&Hs[r0 * FS_X + col]       = make_float2(f_rna(v0), f_rna(v1));
                *(float2*)&Hs[(r0 + 8) * FS_X + col] = make_float2(f_rna(v2), f_rna(v3));
            }
        }
        CP_WAIT0;
        __syncthreads();

        // Y += Hs @ w2_chunk
#pragma unroll 4
        for (int ks = 0; ks < 16; ks++) {
            const int k0 = ks * 8;
            uint32_t a[4][4], bf[4][2];
#pragma unroll
            for (int am = 0; am < 4; am++) {
                const int off = (wm + am * 16 + ly) * FS_X + k0 + lx;
                a[am][0] = __float_as_uint(Hs[off]);
                a[am][1] = __float_as_uint(Hs[off + 8 * FS_X]);
                a[am][2] = __float_as_uint(Hs[off + 4]);
                a[am][3] = __float_as_uint(Hs[off + 8 * FS_X + 4]);
            }
#pragma unroll
            for (int an = 0; an < 4; an++) {
                const int off = (k0 + lx) * FS_W + wn + an * 8 + ly;
                bf[an][0] = __float_as_uint(Ws[off]);
                bf[an][1] = __float_as_uint(Ws[off + 4 * FS_W]);
            }
#pragma unroll
            for (int am = 0; am < 4; am++)
#pragma unroll
                for (int an = 0; an < 4; an++) mma8(yacc[am][an], a[am], bf[an]);
        }
        __syncthreads();

        if (c < 2) {   // issue async load of next w1 chunk
            float* wd = Ws + row * FS_W + seg * 64;
            const float* wsrc = w1e + (size_t)row * DFF + (c + 1) * 128 + seg * 64;
#pragma unroll
            for (int j = 0; j < 64; j += 4) cp16(wd + j, wsrc + j);
            CP_COMMIT;
        }
    }

    // gated scatter-add
#pragma unroll
    for (int am = 0; am < 4; am++) {
        const int r0 = wm + am * 16 + ly;
        const int tok0 = toks[r0], tok1 = toks[r0 + 8];
        const float g0 = Gs[r0], g1 = Gs[r0 + 8];
        float* o0 = g_xout + ((size_t)b * NN + tok0) * DHH;
        float* o1 = g_xout + ((size_t)b * NN + tok1) * DHH;
#pragma unroll
        for (int an = 0; an < 4; an++) {
            const int col = wn + an * 8 + 2 * lx;
            atomicAdd(o0 + col,     yacc[am][an][0] * g0);
            atomicAdd(o0 + col + 1, yacc[am][an][1] * g0);
            atomicAdd(o1 + col,     yacc[am][an][2] * g1);
            atomicAdd(o1 + col + 1, yacc[am][an][3] * g1);
        }
    }
}

// ---------------- launch ----------------------------------------------------
extern "C" void kernel_launch(void* const* d_in, const int* in_sizes, int n_in,
                              void* d_out, int out_size) {
    const float* x      = (const float*)d_in[0];
    const float* choice = (const float*)d_in[1];
    const float* w1     = (const float*)d_in[2];
    const float* w2     = (const float*)d_in[3];
    const float* head   = (const float*)d_in[4];
    const float* merge  = (const float*)d_in[5];
    float* out = (float*)d_out;

    float *x1p, *xop, *xh, *xl, *hh, *hl, *mh, *ml, *w1r, *w2r, *xoh, *xol;
    cudaGetSymbolAddress((void**)&x1p, g_x1);
    cudaGetSymbolAddress((void**)&xop, g_xout);
    cudaGetSymbolAddress((void**)&xh, g_xh);
    cudaGetSymbolAddress((void**)&xl, g_xl);
    cudaGetSymbolAddress((void**)&hh, g_hh);
    cudaGetSymbolAddress((void**)&hl, g_hl);
    cudaGetSymbolAddress((void**)&mh, g_mh);
    cudaGetSymbolAddress((void**)&ml, g_ml);
    cudaGetSymbolAddress((void**)&w1r, g_w1r);
    cudaGetSymbolAddress((void**)&w2r, g_w2r);
    cudaGetSymbolAddress((void**)&xoh, g_xoh);
    cudaGetSymbolAddress((void**)&xol, g_xol);

    cudaFuncSetAttribute(gemm3x_kernel, cudaFuncAttributeMaxDynamicSharedMemorySize,
                         G3_SMEM_BYTES);
    cudaFuncSetAttribute(ffn_tf32_kernel, cudaFuncAttributeMaxDynamicSharedMemorySize,
                         FFN_SMEM_BYTES);

    const size_t nX = (size_t)BB * SS * DD;     // 6291456
    const size_t nW = (size_t)DD * DD;          // 589824
    const size_t nW1 = (size_t)EE * DHH * DFF;  // 1179648

    // tf32 splits / rounds
    split_tf32_kernel<<<(unsigned)(nX / 1024), 256>>>(x, xh, xl, nX);
    split_tf32_kernel<<<(unsigned)(nW / 1024), 256>>>(head, hh, hl, nW);
    split_tf32_kernel<<<(unsigned)(nW / 1024), 256>>>(merge, mh, ml, nW);
    round_tf32_kernel<<<(unsigned)(nW1 / 1024), 256>>>(w1, w1r, nW1);
    round_tf32_kernel<<<(unsigned)(nW1 / 1024), 256>>>(w2, w2r, nW1);

    // 1) head projection (3xTF32, accurate -> selections stable)
    dim3 gproj(DD / 128, (BB * SS) / 128);
    gemm3x_kernel<<<gproj, 256, G3_SMEM_BYTES>>>(xh, xl, hh, hl, x1p,
                                                 BB * SS, DD, DD);

    // 2) gating + softmax (fp32)
    gating_kernel<<<(BB * NN) / 8, 256>>>(choice);

    // 3) per-(b,e) top-K
    topk_kernel<<<BB * EE, 256>>>();

    // 4) zero accumulator
    zero_kernel<<<(BB * NN * DHH) / (256 * 4), 256>>>();

    // 5) fused gather -> FFN (tf32 tensor) -> gated scatter
    dim3 gffn(KK / 128, EE, BB);
    ffn_tf32_kernel<<<gffn, 256, FFN_SMEM_BYTES>>>(w1r, w2r);

    // 6) merge projection (3xTF32)
    split_tf32_kernel<<<(unsigned)(nX / 1024), 256>>>(xop, xoh, xol, nX);
    gemm3x_kernel<<<gproj, 256, G3_SMEM_BYTES>>>(xoh, xol, mh, ml, out,
                                                 BB * SS, DD, DD);
}

// round 6
// speedup vs baseline: 1.6564x; 1.2115x over previous
#include <cuda_runtime.h>
#include <math.h>
#include <stdint.h>

// Problem constants
#define BB  8
#define SS  1024
#define DD  768
#define EE  24
#define DHH 128
#define DFF 384
#define NN  6144          // S*H tokens per batch
#define KK  1024          // tokens per expert

// ---------------- scratch (device globals; no allocation allowed) -----------
__device__ float g_x1[(size_t)BB * NN * DHH];     // head-projected tokens (fp32)
__device__ float g_gates[(size_t)BB * EE * NN];
__device__ int   g_idx[(size_t)BB * EE * KK];
__device__ float g_gateval[(size_t)BB * EE * KK];
__device__ float g_xout[(size_t)BB * NN * DHH];   // scatter accumulator (fp32)

__device__ float g_xh[(size_t)BB * SS * DD];      // x split hi/lo (tf32)
__device__ float g_xl[(size_t)BB * SS * DD];
__device__ float g_hh[DD * DD];                   // head split
__device__ float g_hl[DD * DD];
__device__ float g_w1r[(size_t)EE * DHH * DFF];   // w1 rounded to tf32
__device__ float g_w2r[(size_t)EE * DFF * DHH];   // w2 rounded to tf32

// ---------------- helpers ----------------------------------------------------
__device__ __forceinline__ float f_rna(float x) {
    uint32_t u;
    asm("cvt.rna.tf32.f32 %0, %1;" : "=r"(u) : "f"(x));
    return __uint_as_float(u);
}

__device__ __forceinline__ void mma8(float* c, const uint32_t* a, const uint32_t* b) {
    asm volatile(
        "mma.sync.aligned.m16n8k8.row.col.f32.tf32.tf32.f32 "
        "{%0,%1,%2,%3}, {%4,%5,%6,%7}, {%8,%9}, {%0,%1,%2,%3};\n"
        : "+f"(c[0]), "+f"(c[1]), "+f"(c[2]), "+f"(c[3])
        : "r"(a[0]), "r"(a[1]), "r"(a[2]), "r"(a[3]), "r"(b[0]), "r"(b[1]));
}

__device__ __forceinline__ void cp16(void* smem, const void* g) {
    uint32_t s = (uint32_t)__cvta_generic_to_shared(smem);
    asm volatile("cp.async.ca.shared.global [%0], [%1], 16;" :: "r"(s), "l"(g));
}
#define CP_COMMIT asm volatile("cp.async.commit_group;")
#define CP_WAIT0  asm volatile("cp.async.wait_group 0;")
#define CP_WAIT1  asm volatile("cp.async.wait_group 1;")

// ---------------- elementwise tf32 split / round -----------------------------
__global__ void split_tf32_kernel(const float* __restrict__ src,
                                  float* __restrict__ hi, float* __restrict__ lo,
                                  size_t n) {
    size_t i = ((size_t)blockIdx.x * blockDim.x + threadIdx.x) * 4;
    if (i >= n) return;
    float4 v = *(const float4*)(src + i);
    float4 h, l;
    h.x = f_rna(v.x); l.x = f_rna(v.x - h.x);
    h.y = f_rna(v.y); l.y = f_rna(v.y - h.y);
    h.z = f_rna(v.z); l.z = f_rna(v.z - h.z);
    h.w = f_rna(v.w); l.w = f_rna(v.w - h.w);
    *(float4*)(hi + i) = h;
    *(float4*)(lo + i) = l;
}

__global__ void round_tf32_kernel(const float* __restrict__ src,
                                  float* __restrict__ dst, size_t n) {
    size_t i = ((size_t)blockIdx.x * blockDim.x + threadIdx.x) * 4;
    if (i >= n) return;
    float4 v = *(const float4*)(src + i);
    v.x = f_rna(v.x); v.y = f_rna(v.y); v.z = f_rna(v.z); v.w = f_rna(v.w);
    *(float4*)(dst + i) = v;
}

// ---------------- 3xTF32 GEMM (head proj): C = A@B --------------------------
// block 128x128, 8 warps (warp 64x32), K-tile 32, cp.async double buffer.
#define SA 36
#define SB 136
#define G3_A  (128 * SA)
#define G3_B  (32 * SB)
#define G3_BUF (2 * G3_A + 2 * G3_B)
#define G3_SMEM_BYTES (2 * G3_BUF * 4)

__global__ __launch_bounds__(256) void gemm3x_kernel(
    const float* __restrict__ Ah, const float* __restrict__ Al,
    const float* __restrict__ Bh, const float* __restrict__ Bl,
    float* __restrict__ C, int M, int N, int K)
{
    extern __shared__ float sm[];
    const int tid = threadIdx.x;
    const int bm = blockIdx.y * 128, bn = blockIdx.x * 128;

    const int ar = tid & 127, aseg = tid >> 7;
    const int br = tid & 31,  bseg = tid >> 5;

    const int warp = tid >> 5, lane = tid & 31;
    const int wm = (warp >> 2) * 64, wn = (warp & 3) * 32;
    const int ly = lane >> 2, lx = lane & 3;

    const int T = K / 32;

    auto stage = [&](int buf, int kt) {
        float* base = sm + buf * G3_BUF;
        float* ahd = base + ar * SA + aseg * 16;
        float* ald = base + G3_A + ar * SA + aseg * 16;
        const float* ahs = Ah + (size_t)(bm + ar) * K + kt * 32 + aseg * 16;
        const float* als = Al + (size_t)(bm + ar) * K + kt * 32 + aseg * 16;
#pragma unroll
        for (int j = 0; j < 16; j += 4) { cp16(ahd + j, ahs + j); cp16(ald + j, als + j); }
        float* bhd = base + 2 * G3_A + br * SB + bseg * 16;
        float* bld = base + 2 * G3_A + G3_B + br * SB + bseg * 16;
        const float* bhs = Bh + (size_t)(kt * 32 + br) * N + bn + bseg * 16;
        const float* bls = Bl + (size_t)(kt * 32 + br) * N + bn + bseg * 16;
#pragma unroll
        for (int j = 0; j < 16; j += 4) { cp16(bhd + j, bhs + j); cp16(bld + j, bls + j); }
    };

    float c[4][4][4];
#pragma unroll
    for (int i = 0; i < 4; i++)
#pragma unroll
        for (int j = 0; j < 4; j++)
#pragma unroll
            for (int k = 0; k < 4; k++) c[i][j][k] = 0.f;

    stage(0, 0);
    CP_COMMIT;

    for (int t = 0; t < T; t++) {
        if (t + 1 < T) { stage((t + 1) & 1, t + 1); CP_COMMIT; CP_WAIT1; }
        else           { CP_WAIT0; }
        __syncthreads();
        const float* base = sm + (t & 1) * G3_BUF;
        const float* Ash = base;
        const float* Asl = base + G3_A;
        const float* Bsh = base + 2 * G3_A;
        const float* Bsl = base + 2 * G3_A + G3_B;
#pragma unroll
        for (int ks = 0; ks < 4; ks++) {
            const int k0 = ks * 8;
            uint32_t ah[4][4], al[4][4], bh[4][2], bl[4][2];
#pragma unroll
            for (int am = 0; am < 4; am++) {
                const int off = (wm + am * 16 + ly) * SA + k0 + lx;
                ah[am][0] = __float_as_uint(Ash[off]);
                ah[am][1] = __float_as_uint(Ash[off + 8 * SA]);
                ah[am][2] = __float_as_uint(Ash[off + 4]);
                ah[am][3] = __float_as_uint(Ash[off + 8 * SA + 4]);
                al[am][0] = __float_as_uint(Asl[off]);
                al[am][1] = __float_as_uint(Asl[off + 8 * SA]);
                al[am][2] = __float_as_uint(Asl[off + 4]);
                al[am][3] = __float_as_uint(Asl[off + 8 * SA + 4]);
            }
#pragma unroll
            for (int an = 0; an < 4; an++) {
                const int off = (k0 + lx) * SB + wn + an * 8 + ly;
                bh[an][0] = __float_as_uint(Bsh[off]);
                bh[an][1] = __float_as_uint(Bsh[off + 4 * SB]);
                bl[an][0] = __float_as_uint(Bsl[off]);
                bl[an][1] = __float_as_uint(Bsl[off + 4 * SB]);
            }
#pragma unroll
            for (int am = 0; am < 4; am++)
#pragma unroll
                for (int an = 0; an < 4; an++) {
                    mma8(c[am][an], ah[am], bh[an]);
                    mma8(c[am][an], ah[am], bl[an]);
                    mma8(c[am][an], al[am], bh[an]);
                }
        }
        __syncthreads();
    }

#pragma unroll
    for (int am = 0; am < 4; am++) {
        const int row = bm + wm + am * 16 + ly;
#pragma unroll
        for (int an = 0; an < 4; an++) {
            const int col = bn + wn + an * 8 + 2 * lx;
            *(float2*)(C + (size_t)row * N + col)       = make_float2(c[am][an][0], c[am][an][1]);
            *(float2*)(C + (size_t)(row + 8) * N + col) = make_float2(c[am][an][2], c[am][an][3]);
        }
    }
}

// ---------------- single-pass tf32 GEMM (merge proj): C = rna(A)@rna(B) ------
// 128x128 tile, 256 threads, on-the-fly rounding in staging, reg-prefetch
// double buffer, 70KB smem -> 2 CTAs/SM.
#define MG_A (128 * SA)                 // 4608
#define MG_B (32 * SB)                  // 4352
#define MG_BUF (MG_A + MG_B)            // 8960 floats
#define MG_SMEM_BYTES (2 * MG_BUF * 4)  // 71680 B

__global__ __launch_bounds__(256, 2) void gemm1x_kernel(
    const float* __restrict__ A, const float* __restrict__ B,
    float* __restrict__ C, int M, int N, int K)
{
    extern __shared__ float sm[];
    const int tid = threadIdx.x;
    const int bm = blockIdx.y * 128, bn = blockIdx.x * 128;

    const int ar = tid >> 1, ac0 = (tid & 1) * 16;   // A: 128 rows x 32 cols
    const int br = tid >> 3, bc0 = (tid & 7) * 16;   // B: 32 rows x 128 cols

    const int warp = tid >> 5, lane = tid & 31;
    const int wm = (warp >> 2) * 64, wn = (warp & 3) * 32;
    const int ly = lane >> 2, lx = lane & 3;

    const int T = K / 32;

    float4 aR[4], bR[4];
    auto ldg = [&](int kt) {
        const float* as = A + (size_t)(bm + ar) * K + kt * 32 + ac0;
        const float* bs = B + (size_t)(kt * 32 + br) * N + bn + bc0;
#pragma unroll
        for (int j = 0; j < 4; j++) aR[j] = *(const float4*)(as + 4 * j);
#pragma unroll
        for (int j = 0; j < 4; j++) bR[j] = *(const float4*)(bs + 4 * j);
    };
    auto sts = [&](int buf) {
        float* Ad = sm + buf * MG_BUF + ar * SA + ac0;
        float* Bd = sm + buf * MG_BUF + MG_A + br * SB + bc0;
#pragma unroll
        for (int j = 0; j < 4; j++) {
            float4 v = aR[j];
            *(float4*)(Ad + 4 * j) = make_float4(f_rna(v.x), f_rna(v.y), f_rna(v.z), f_rna(v.w));
        }
#pragma unroll
        for (int j = 0; j < 4; j++) {
            float4 v = bR[j];
            *(float4*)(Bd + 4 * j) = make_float4(f_rna(v.x), f_rna(v.y), f_rna(v.z), f_rna(v.w));
        }
    };

    float c[4][4][4];
#pragma unroll
    for (int i = 0; i < 4; i++)
#pragma unroll
        for (int j = 0; j < 4; j++)
#pragma unroll
            for (int k = 0; k < 4; k++) c[i][j][k] = 0.f;

    ldg(0);
    sts(0);
    __syncthreads();

    for (int t = 0; t < T; t++) {
        if (t + 1 < T) ldg(t + 1);
        const float* base = sm + (t & 1) * MG_BUF;
        const float* As = base;
        const float* Bs = base + MG_A;
#pragma unroll
        for (int ks = 0; ks < 4; ks++) {
            const int k0 = ks * 8;
            uint32_t a[4][4], bf[4][2];
#pragma unroll
            for (int am = 0; am < 4; am++) {
                const int off = (wm + am * 16 + ly) * SA + k0 + lx;
                a[am][0] = __float_as_uint(As[off]);
                a[am][1] = __float_as_uint(As[off + 8 * SA]);
                a[am][2] = __float_as_uint(As[off + 4]);
                a[am][3] = __float_as_uint(As[off + 8 * SA + 4]);
            }
#pragma unroll
            for (int an = 0; an < 4; an++) {
                const int off = (k0 + lx) * SB + wn + an * 8 + ly;
                bf[an][0] = __float_as_uint(Bs[off]);
                bf[an][1] = __float_as_uint(Bs[off + 4 * SB]);
            }
#pragma unroll
            for (int am = 0; am < 4; am++)
#pragma unroll
                for (int an = 0; an < 4; an++) mma8(c[am][an], a[am], bf[an]);
        }
        if (t + 1 < T) {
            sts((t + 1) & 1);
            __syncthreads();
        }
    }

#pragma unroll
    for (int am = 0; am < 4; am++) {
        const int row = bm + wm + am * 16 + ly;
#pragma unroll
        for (int an = 0; an < 4; an++) {
            const int col = bn + wn + an * 8 + 2 * lx;
            *(float2*)(C + (size_t)row * N + col)       = make_float2(c[am][an][0], c[am][an][1]);
            *(float2*)(C + (size_t)(row + 8) * N + col) = make_float2(c[am][an][2], c[am][an][3]);
        }
    }
}

// ---------------- gating: logits = x1 . choice^T ; softmax over E -----------
__global__ __launch_bounds__(256) void gating_kernel(const float* __restrict__ choice) {
    __shared__ float cs[EE * DHH];
    for (int i = threadIdx.x; i < EE * DHH; i += 256) cs[i] = choice[i];
    __syncthreads();

    const int warp = threadIdx.x >> 5;
    const int lane = threadIdx.x & 31;
    const long token = (long)blockIdx.x * 8 + warp;
    if (token >= (long)BB * NN) return;

    const float* xr = g_x1 + token * DHH;
    float4 xv = ((const float4*)xr)[lane];

    float l[EE];
#pragma unroll
    for (int e = 0; e < EE; e++) {
        float4 cv = ((const float4*)(cs + e * DHH))[lane];
        float p = xv.x * cv.x + xv.y * cv.y + xv.z * cv.z + xv.w * cv.w;
#pragma unroll
        for (int o = 16; o > 0; o >>= 1) p += __shfl_xor_sync(0xffffffffu, p, o);
        l[e] = p;
    }
    float m = l[0];
#pragma unroll
    for (int e = 1; e < EE; e++) m = fmaxf(m, l[e]);
    float s = 0.f;
#pragma unroll
    for (int e = 0; e < EE; e++) { l[e] = expf(l[e] - m); s += l[e]; }
    const float inv = 1.f / s;
    const int b = (int)(token / NN);
    const int n = (int)(token % NN);
    if (lane < EE)
        g_gates[((size_t)b * EE + lane) * NN + n] = l[lane] * inv;
}

// ---------------- deterministic top-K per (b,e) via radix select ------------
__global__ __launch_bounds__(256) void topk_kernel() {
    __shared__ unsigned sv[NN];
    __shared__ int red[256];
    __shared__ int cnts[256];
    __shared__ int gtoff[256];
    __shared__ int eqoff[256];
    __shared__ int tot_gt;

    const int be = blockIdx.x;
    const int tid = threadIdx.x;
    const float* g = g_gates + (size_t)be * NN;
    for (int i = tid; i < NN; i += 256) sv[i] = __float_as_uint(g[i]);
    __syncthreads();

    unsigned thr = 0u;
    for (int bit = 30; bit >= 0; bit--) {
        unsigned cand = thr | (1u << bit);
        int c = 0;
        for (int i = tid; i < NN; i += 256) c += (sv[i] >= cand) ? 1 : 0;
        red[tid] = c;
        __syncthreads();
        for (int s = 128; s > 0; s >>= 1) {
            if (tid < s) red[tid] += red[tid + s];
            __syncthreads();
        }
        int tot = red[0];
        __syncthreads();
        if (tot >= KK) thr = cand;
    }

    const int base = tid * (NN / 256);
    int lgt = 0, leq = 0;
#pragma unroll
    for (int j = 0; j < NN / 256; j++) {
        unsigned v = sv[base + j];
        lgt += (v > thr);
        leq += (v == thr);
    }
    red[tid] = lgt;
    cnts[tid] = leq;
    __syncthreads();
    if (tid == 0) {
        int a = 0;
        for (int i = 0; i < 256; i++) { gtoff[i] = a; a += red[i]; }
        tot_gt = a;
        a = 0;
        for (int i = 0; i < 256; i++) { eqoff[i] = a; a += cnts[i]; }
    }
    __syncthreads();

    const int ngt = tot_gt;
    int pgt = gtoff[tid];
    int peq = ngt + eqoff[tid];
    int*   ip = g_idx     + (size_t)be * KK;
    float* gp = g_gateval + (size_t)be * KK;
#pragma unroll
    for (int j = 0; j < NN / 256; j++) {
        unsigned v = sv[base + j];
        if (v > thr) {
            ip[pgt] = base + j;
            gp[pgt] = __uint_as_float(v);
            pgt++;
        } else if (v == thr) {
            if (peq < KK) {
                ip[peq] = base + j;
                gp[peq] = __uint_as_float(v);
            }
            peq++;
        }
    }
}

// ---------------- zero accumulator ------------------------------------------
__global__ void zero_kernel() {
    size_t i = ((size_t)blockIdx.x * blockDim.x + threadIdx.x) * 4;
    if (i < (size_t)BB * NN * DHH) {
        *(float4*)(g_xout + i) = make_float4(0.f, 0.f, 0.f, 0.f);
    }
}

// ---------------- fused gather -> FFN (tf32 mma) -> gated scatter ------------
// block = (token_tile 128, expert, batch), 512 threads, 16 warps (warp 32x32).
#define FS_X 132
#define FS_W 136
#define FFN_XS   (128 * FS_X)
#define FFN_WS   (128 * FS_W)
#define FFN_SMEM_FLOATS (2 * FFN_XS + FFN_WS + 256)
#define FFN_SMEM_BYTES (FFN_SMEM_FLOATS * 4)

__global__ __launch_bounds__(512, 1) void ffn_tf32_kernel(const float* __restrict__ w1r,
                                                          const float* __restrict__ w2r) {
    extern __shared__ float sm[];
    float* Xs = sm;
    float* Hs = sm + FFN_XS;
    float* Ws = sm + 2 * FFN_XS;
    int*   toks = (int*)(sm + 2 * FFN_XS + FFN_WS);
    float* Gs   = sm + 2 * FFN_XS + FFN_WS + 128;

    const int tile = blockIdx.x, e = blockIdx.y, b = blockIdx.z;
    const int tid = threadIdx.x;
    const int be = b * EE + e;
    const int* idxp = g_idx + (size_t)be * KK + tile * 128;
    const float* gvp = g_gateval + (size_t)be * KK + tile * 128;
    const float* w1e = w1r + (size_t)e * DHH * DFF;
    const float* w2e = w2r + (size_t)e * DFF * DHH;

    const int row = tid >> 2, seg = tid & 3;   // 512 threads: 128 rows x 4 segs of 32

    // prologue: issue async load of w1 chunk 0
    {
        float* wd = Ws + row * FS_W + seg * 32;
        const float* wsrc = w1e + (size_t)row * DFF + seg * 32;
#pragma unroll
        for (int j = 0; j < 32; j += 4) cp16(wd + j, wsrc + j);
    }
    CP_COMMIT;

    // gather X (convert to tf32 while staging)
    {
        const int tok = idxp[row];
        if (seg == 0) { toks[row] = tok; Gs[row] = gvp[row]; }
        const float* xr = g_x1 + ((size_t)b * NN + tok) * DHH + seg * 32;
        float* xd = Xs + row * FS_X + seg * 32;
#pragma unroll
        for (int j = 0; j < 32; j += 4) {
            float4 v = *(const float4*)(xr + j);
            xd[j]     = f_rna(v.x);
            xd[j + 1] = f_rna(v.y);
            xd[j + 2] = f_rna(v.z);
            xd[j + 3] = f_rna(v.w);
        }
    }

    const int warp = tid >> 5, lane = tid & 31;
    const int wm = (warp >> 2) * 32, wn = (warp & 3) * 32;
    const int ly = lane >> 2, lx = lane & 3;

    float yacc[2][4][4];
#pragma unroll
    for (int i = 0; i < 2; i++)
#pragma unroll
        for (int j = 0; j < 4; j++)
#pragma unroll
            for (int k = 0; k < 4; k++) yacc[i][j][k] = 0.f;

    for (int c = 0; c < 3; c++) {
        CP_WAIT0;
        __syncthreads();

        // H = Xs @ w1_chunk
        float h[2][4][4];
#pragma unroll
        for (int i = 0; i < 2; i++)
#pragma unroll
            for (int j = 0; j < 4; j++)
#pragma unroll
                for (int k = 0; k < 4; k++) h[i][j][k] = 0.f;

#pragma unroll 4
        for (int ks = 0; ks < 16; ks++) {
            const int k0 = ks * 8;
            uint32_t a[2][4], bf[4][2];
#pragma unroll
            for (int am = 0; am < 2; am++) {
                const int off = (wm + am * 16 + ly) * FS_X + k0 + lx;
                a[am][0] = __float_as_uint(Xs[off]);
                a[am][1] = __float_as_uint(Xs[off + 8 * FS_X]);
                a[am][2] = __float_as_uint(Xs[off + 4]);
                a[am][3] = __float_as_uint(Xs[off + 8 * FS_X + 4]);
            }
#pragma unroll
            for (int an = 0; an < 4; an++) {
                const int off = (k0 + lx) * FS_W + wn + an * 8 + ly;
                bf[an][0] = __float_as_uint(Ws[off]);
                bf[an][1] = __float_as_uint(Ws[off + 4 * FS_W]);
            }
#pragma unroll
            for (int am = 0; am < 2; am++)
#pragma unroll
                for (int an = 0; an < 4; an++) mma8(h[am][an], a[am], bf[an]);
        }
        __syncthreads();   // done reading w1 chunk

        // issue async load of w2 chunk c (overlaps silu below)
        {
            float* wd = Ws + row * FS_W + seg * 32;
            const float* wsrc = w2e + (size_t)(c * 128 + row) * DHH + seg * 32;
#pragma unroll
            for (int j = 0; j < 32; j += 4) cp16(wd + j, wsrc + j);
        }
        CP_COMMIT;

        // silu -> Hs (tf32-rounded)
#pragma unroll
        for (int am = 0; am < 2; am++) {
            const int r0 = wm + am * 16 + ly;
#pragma unroll
            for (int an = 0; an < 4; an++) {
                const int col = wn + an * 8 + 2 * lx;
                float v0 = h[am][an][0], v1 = h[am][an][1];
                float v2 = h[am][an][2], v3 = h[am][an][3];
                v0 = v0 / (1.f + expf(-v0));
                v1 = v1 / (1.f + expf(-v1));
                v2 = v2 / (1.f + expf(-v2));
                v3 = v3 / (1.f + expf(-v3));
                *(float2*)&Hs[r0 * FS_X + col]       = make_float2(f_rna(v0), f_rna(v1));
                *(float2*)&Hs[(r0 + 8) * FS_X + col] = make_float2(f_rna(v2), f_rna(v3));
            }
        }
        CP_WAIT0;
        __syncthreads();

        // Y += Hs @ w2_chunk
#pragma unroll 4
        for (int ks = 0; ks < 16; ks++) {
            const int k0 = ks * 8;
            uint32_t a[2][4], bf[4][2];
#pragma unroll
            for (int am = 0; am < 2; am++) {
                const int off = (wm + am * 16 + ly) * FS_X + k0 + lx;
                a[am][0] = __float_as_uint(Hs[off]);
                a[am][1] = __float_as_uint(Hs[off + 8 * FS_X]);
                a[am][2] = __float_as_uint(Hs[off + 4]);
                a[am][3] = __float_as_uint(Hs[off + 8 * FS_X + 4]);
            }
#pragma unroll
            for (int an = 0; an < 4; an++) {
                const int off = (k0 + lx) * FS_W + wn + an * 8 + ly;
                bf[an][0] = __float_as_uint(Ws[off]);
                bf[an][1] = __float_as_uint(Ws[off + 4 * FS_W]);
            }
#pragma unroll
            for (int am = 0; am < 2; am++)
#pragma unroll
                for (int an = 0; an < 4; an++) mma8(yacc[am][an], a[am], bf[an]);
        }
        __syncthreads();

        if (c < 2) {   // issue async load of next w1 chunk
            float* wd = Ws + row * FS_W + seg * 32;
            const float* wsrc = w1e + (size_t)row * DFF + (c + 1) * 128 + seg * 32;
#pragma unroll
            for (int j = 0; j < 32; j += 4) cp16(wd + j, wsrc + j);
            CP_COMMIT;
        }
    }

    // gated scatter-add
#pragma unroll
    for (int am = 0; am < 2; am++) {
        const int r0 = wm + am * 16 + ly;
        const int tok0 = toks[r0], tok1 = toks[r0 + 8];
        const float g0 = Gs[r0], g1 = Gs[r0 + 8];
        float* o0 = g_xout + ((size_t)b * NN + tok0) * DHH;
        float* o1 = g_xout + ((size_t)b * NN + tok1) * DHH;
#pragma unroll
        for (int an = 0; an < 4; an++) {
            const int col = wn + an * 8 + 2 * lx;
            atomicAdd(o0 + col,     yacc[am][an][0] * g0);
            atomicAdd(o0 + col + 1, yacc[am][an][1] * g0);
            atomicAdd(o1 + col,     yacc[am][an][2] * g1);
            atomicAdd(o1 + col + 1, yacc[am][an][3] * g1);
        }
    }
}

// ---------------- launch ----------------------------------------------------
extern "C" void kernel_launch(void* const* d_in, const int* in_sizes, int n_in,
                              void* d_out, int out_size) {
    const float* x      = (const float*)d_in[0];
    const float* choice = (const float*)d_in[1];
    const float* w1     = (const float*)d_in[2];
    const float* w2     = (const float*)d_in[3];
    const float* head   = (const float*)d_in[4];
    const float* merge  = (const float*)d_in[5];
    float* out = (float*)d_out;

    float *x1p, *xop, *xh, *xl, *hh, *hl, *w1r, *w2r;
    cudaGetSymbolAddress((void**)&x1p, g_x1);
    cudaGetSymbolAddress((void**)&xop, g_xout);
    cudaGetSymbolAddress((void**)&xh, g_xh);
    cudaGetSymbolAddress((void**)&xl, g_xl);
    cudaGetSymbolAddress((void**)&hh, g_hh);
    cudaGetSymbolAddress((void**)&hl, g_hl);
    cudaGetSymbolAddress((void**)&w1r, g_w1r);
    cudaGetSymbolAddress((void**)&w2r, g_w2r);

    cudaFuncSetAttribute(gemm3x_kernel, cudaFuncAttributeMaxDynamicSharedMemorySize,
                         G3_SMEM_BYTES);
    cudaFuncSetAttribute(gemm1x_kernel, cudaFuncAttributeMaxDynamicSharedMemorySize,
                         MG_SMEM_BYTES);
    cudaFuncSetAttribute(ffn_tf32_kernel, cudaFuncAttributeMaxDynamicSharedMemorySize,
                         FFN_SMEM_BYTES);

    const size_t nX = (size_t)BB * SS * DD;     // 6291456
    const size_t nW = (size_t)DD * DD;          // 589824
    const size_t nW1 = (size_t)EE * DHH * DFF;  // 1179648

    // tf32 splits / rounds (head-path only; merge rounds on the fly)
    split_tf32_kernel<<<(unsigned)(nX / 1024), 256>>>(x, xh, xl, nX);
    split_tf32_kernel<<<(unsigned)(nW / 1024), 256>>>(head, hh, hl, nW);
    round_tf32_kernel<<<(unsigned)(nW1 / 1024), 256>>>(w1, w1r, nW1);
    round_tf32_kernel<<<(unsigned)(nW1 / 1024), 256>>>(w2, w2r, nW1);

    // 1) head projection (3xTF32, accurate -> selections stable)
    dim3 gproj(DD / 128, (BB * SS) / 128);
    gemm3x_kernel<<<gproj, 256, G3_SMEM_BYTES>>>(xh, xl, hh, hl, x1p,
                                                 BB * SS, DD, DD);

    // 2) gating + softmax (fp32)
    gating_kernel<<<(BB * NN) / 8, 256>>>(choice);

    // 3) per-(b,e) top-K
    topk_kernel<<<BB * EE, 256>>>();

    // 4) zero accumulator
    zero_kernel<<<(BB * NN * DHH) / (256 * 4), 256>>>();

    // 5) fused gather -> FFN (tf32 tensor) -> gated scatter
    dim3 gffn(KK / 128, EE, BB);
    ffn_tf32_kernel<<<gffn, 512, FFN_SMEM_BYTES>>>(w1r, w2r);

    // 6) merge projection (single-pass tf32, on-the-fly rounding)
    gemm1x_kernel<<<gproj, 256, MG_SMEM_BYTES>>>(xop, merge, out,
                                                 BB * SS, DD, DD);
}

// round 10
// speedup vs baseline: 1.8511x; 1.1175x over previous
#include <cuda_runtime.h>
#include <math.h>
#include <stdint.h>

// Problem constants
#define BB  8
#define SS  1024
#define DD  768
#define EE  24
#define DHH 128
#define DFF 384
#define NN  6144          // S*H tokens per batch
#define KK  1024          // tokens per expert
#define HH  6             // heads

// ---------------- scratch (device globals; no allocation allowed) -----------
__device__ float g_x1[(size_t)BB * NN * DHH];     // head-projected tokens (tf32-accurate)
__device__ float g_gates[(size_t)BB * EE * NN];
__device__ int   g_idx[(size_t)BB * EE * KK];
__device__ float g_gateval[(size_t)BB * EE * KK];
__device__ float g_xout[(size_t)BB * NN * DHH];   // scatter accumulator (fp32)
__device__ float g_W[DD * HH * EE];               // fused gating matrix [768][144]
__device__ float g_w1r[(size_t)EE * DHH * DFF];   // w1 rounded to tf32
__device__ float g_w2r[(size_t)EE * DFF * DHH];   // w2 rounded to tf32

// ---------------- helpers ----------------------------------------------------
__device__ __forceinline__ float f_rna(float x) {
    uint32_t u;
    asm("cvt.rna.tf32.f32 %0, %1;" : "=r"(u) : "f"(x));
    return __uint_as_float(u);
}

__device__ __forceinline__ void mma8(float* c, const uint32_t* a, const uint32_t* b) {
    asm volatile(
        "mma.sync.aligned.m16n8k8.row.col.f32.tf32.tf32.f32 "
        "{%0,%1,%2,%3}, {%4,%5,%6,%7}, {%8,%9}, {%0,%1,%2,%3};\n"
        : "+f"(c[0]), "+f"(c[1]), "+f"(c[2]), "+f"(c[3])
        : "r"(a[0]), "r"(a[1]), "r"(a[2]), "r"(a[3]), "r"(b[0]), "r"(b[1]));
}

__device__ __forceinline__ void cp16(void* smem, const void* g) {
    uint32_t s = (uint32_t)__cvta_generic_to_shared(smem);
    asm volatile("cp.async.ca.shared.global [%0], [%1], 16;" :: "r"(s), "l"(g));
}
#define CP_COMMIT asm volatile("cp.async.commit_group;")
#define CP_WAIT0  asm volatile("cp.async.wait_group 0;")

// ---------------- elementwise tf32 round -------------------------------------
__global__ void round_tf32_kernel(const float* __restrict__ src,
                                  float* __restrict__ dst, size_t n) {
    size_t i = ((size_t)blockIdx.x * blockDim.x + threadIdx.x) * 4;
    if (i >= n) return;
    float4 v = *(const float4*)(src + i);
    v.x = f_rna(v.x); v.y = f_rna(v.y); v.z = f_rna(v.z); v.w = f_rna(v.w);
    *(float4*)(dst + i) = v;
}

// ---------------- fused gating matrix: W[d][h*24+e] --------------------------
// W[d][h,e] = sum_o head[d][h*128+o] * choice[e][o]   (exact fp32)
__global__ __launch_bounds__(144) void choice_proj_kernel(
    const float* __restrict__ head, const float* __restrict__ choice)
{
    __shared__ float hs[DD];
    __shared__ float cs[EE * DHH];
    const int d = blockIdx.x;
    for (int i = threadIdx.x; i < DD; i += 144) hs[i] = head[(size_t)d * DD + i];
    for (int i = threadIdx.x; i < EE * DHH; i += 144) cs[i] = choice[i];
    __syncthreads();
    const int h = threadIdx.x / EE, e = threadIdx.x % EE;
    float a = 0.f;
#pragma unroll 8
    for (int o = 0; o < DHH; o++) a += hs[h * DHH + o] * cs[e * DHH + o];
    g_W[d * (HH * EE) + threadIdx.x] = a;
}

// ---------------- logits (fp32 SIMT GEMM) + softmax --------------------------
// block: 64 x-rows x 144 cols, 384 threads (thread = 4 rows x 6 cols),
// then fused per-(row,h) softmax over 24 experts.
#define LG_XS 0
#define LG_WS 2112
#define LG_LS (2112 + 4640)
#define LG_SMEM_BYTES ((2112 + 4640 + 64 * 145) * 4)

__global__ __launch_bounds__(384) void logits_softmax_kernel(const float* __restrict__ x) {
    extern __shared__ float sm[];
    float* Xs = sm + LG_XS;   // [64][33]
    float* Ws = sm + LG_WS;   // [32][145]
    float* Ls = sm + LG_LS;   // [64][145]
    const int tid = threadIdx.x;
    const int row0 = blockIdx.x * 64;
    const int ry = tid / 24, cx = tid % 24;   // ry 0..15, cx 0..23

    float acc[4][6];
#pragma unroll
    for (int i = 0; i < 4; i++)
#pragma unroll
        for (int j = 0; j < 6; j++) acc[i][j] = 0.f;

    for (int k0 = 0; k0 < DD; k0 += 32) {
        for (int i = tid; i < 64 * 32; i += 384) {
            int r = i >> 5, c = i & 31;
            Xs[r * 33 + c] = x[(size_t)(row0 + r) * DD + k0 + c];
        }
        for (int i = tid; i < 32 * 144; i += 384) {
            int r = i / 144, c = i % 144;
            Ws[r * 145 + c] = g_W[(k0 + r) * 144 + c];
        }
        __syncthreads();
#pragma unroll 8
        for (int kk = 0; kk < 32; kk++) {
            float xv[4], wv[6];
#pragma unroll
            for (int i = 0; i < 4; i++) xv[i] = Xs[(ry * 4 + i) * 33 + kk];
#pragma unroll
            for (int j = 0; j < 6; j++) wv[j] = Ws[kk * 145 + cx * 6 + j];
#pragma unroll
            for (int i = 0; i < 4; i++)
#pragma unroll
                for (int j = 0; j < 6; j++) acc[i][j] += xv[i] * wv[j];
        }
        __syncthreads();
    }
#pragma unroll
    for (int i = 0; i < 4; i++)
#pragma unroll
        for (int j = 0; j < 6; j++)
            Ls[(ry * 4 + i) * 145 + cx * 6 + j] = acc[i][j];
    __syncthreads();

    // softmax per (row, h): task tid -> r = tid/6, h = tid%6
    {
        const int r = tid / 6, h = tid % 6;
        const int row = row0 + r;
        const int b = row / SS, s = row % SS;
        const int n = s * HH + h;
        float l[EE];
        float m = -1e30f;
#pragma unroll
        for (int e = 0; e < EE; e++) {
            l[e] = Ls[r * 145 + h * EE + e];
            m = fmaxf(m, l[e]);
        }
        float sum = 0.f;
#pragma unroll
        for (int e = 0; e < EE; e++) { l[e] = expf(l[e] - m); sum += l[e]; }
        const float inv = 1.f / sum;
#pragma unroll
        for (int e = 0; e < EE; e++)
            g_gates[((size_t)(b * EE + e)) * NN + n] = l[e] * inv;
    }
}

// ---------------- single-pass tf32 GEMM (head + merge proj) ------------------
// 128x128 tile, 256 threads, on-the-fly rna rounding, reg-prefetch double
// buffer, 70KB smem -> 2 CTAs/SM.
#define SA 36
#define SB 136
#define MG_A (128 * SA)
#define MG_B (32 * SB)
#define MG_BUF (MG_A + MG_B)
#define MG_SMEM_BYTES (2 * MG_BUF * 4)

__global__ __launch_bounds__(256, 2) void gemm1x_kernel(
    const float* __restrict__ A, const float* __restrict__ B,
    float* __restrict__ C, int M, int N, int K)
{
    extern __shared__ float sm[];
    const int tid = threadIdx.x;
    const int bm = blockIdx.y * 128, bn = blockIdx.x * 128;

    const int ar = tid >> 1, ac0 = (tid & 1) * 16;
    const int br = tid >> 3, bc0 = (tid & 7) * 16;

    const int warp = tid >> 5, lane = tid & 31;
    const int wm = (warp >> 2) * 64, wn = (warp & 3) * 32;
    const int ly = lane >> 2, lx = lane & 3;

    const int T = K / 32;

    float4 aR[4], bR[4];
    auto ldg = [&](int kt) {
        const float* as = A + (size_t)(bm + ar) * K + kt * 32 + ac0;
        const float* bs = B + (size_t)(kt * 32 + br) * N + bn + bc0;
#pragma unroll
        for (int j = 0; j < 4; j++) aR[j] = *(const float4*)(as + 4 * j);
#pragma unroll
        for (int j = 0; j < 4; j++) bR[j] = *(const float4*)(bs + 4 * j);
    };
    auto sts = [&](int buf) {
        float* Ad = sm + buf * MG_BUF + ar * SA + ac0;
        float* Bd = sm + buf * MG_BUF + MG_A + br * SB + bc0;
#pragma unroll
        for (int j = 0; j < 4; j++) {
            float4 v = aR[j];
            *(float4*)(Ad + 4 * j) = make_float4(f_rna(v.x), f_rna(v.y), f_rna(v.z), f_rna(v.w));
        }
#pragma unroll
        for (int j = 0; j < 4; j++) {
            float4 v = bR[j];
            *(float4*)(Bd + 4 * j) = make_float4(f_rna(v.x), f_rna(v.y), f_rna(v.z), f_rna(v.w));
        }
    };

    float c[4][4][4];
#pragma unroll
    for (int i = 0; i < 4; i++)
#pragma unroll
        for (int j = 0; j < 4; j++)
#pragma unroll
            for (int k = 0; k < 4; k++) c[i][j][k] = 0.f;

    ldg(0);
    sts(0);
    __syncthreads();

    for (int t = 0; t < T; t++) {
        if (t + 1 < T) ldg(t + 1);
        const float* base = sm + (t & 1) * MG_BUF;
        const float* As = base;
        const float* Bs = base + MG_A;
#pragma unroll
        for (int ks = 0; ks < 4; ks++) {
            const int k0 = ks * 8;
            uint32_t a[4][4], bf[4][2];
#pragma unroll
            for (int am = 0; am < 4; am++) {
                const int off = (wm + am * 16 + ly) * SA + k0 + lx;
                a[am][0] = __float_as_uint(As[off]);
                a[am][1] = __float_as_uint(As[off + 8 * SA]);
                a[am][2] = __float_as_uint(As[off + 4]);
                a[am][3] = __float_as_uint(As[off + 8 * SA + 4]);
            }
#pragma unroll
            for (int an = 0; an < 4; an++) {
                const int off = (k0 + lx) * SB + wn + an * 8 + ly;
                bf[an][0] = __float_as_uint(Bs[off]);
                bf[an][1] = __float_as_uint(Bs[off + 4 * SB]);
            }
#pragma unroll
            for (int am = 0; am < 4; am++)
#pragma unroll
                for (int an = 0; an < 4; an++) mma8(c[am][an], a[am], bf[an]);
        }
        if (t + 1 < T) {
            sts((t + 1) & 1);
            __syncthreads();
        }
    }

#pragma unroll
    for (int am = 0; am < 4; am++) {
        const int row = bm + wm + am * 16 + ly;
#pragma unroll
        for (int an = 0; an < 4; an++) {
            const int col = bn + wn + an * 8 + 2 * lx;
            *(float2*)(C + (size_t)row * N + col)       = make_float2(c[am][an][0], c[am][an][1]);
            *(float2*)(C + (size_t)(row + 8) * N + col) = make_float2(c[am][an][2], c[am][an][3]);
        }
    }
}

// ---------------- deterministic top-K per (b,e) ------------------------------
__global__ __launch_bounds__(256) void topk_kernel() {
    __shared__ unsigned sv[NN];
    __shared__ int red[256];
    __shared__ int cnts[256];
    __shared__ int gtoff[256];
    __shared__ int eqoff[256];
    __shared__ int tot_gt;

    const int be = blockIdx.x;
    const int tid = threadIdx.x;
    const float* g = g_gates + (size_t)be * NN;
    for (int i = tid; i < NN; i += 256) sv[i] = __float_as_uint(g[i]);
    __syncthreads();

    unsigned thr = 0u;
    for (int bit = 30; bit >= 0; bit--) {
        unsigned cand = thr | (1u << bit);
        int c = 0;
        for (int i = tid; i < NN; i += 256) c += (sv[i] >= cand) ? 1 : 0;
        red[tid] = c;
        __syncthreads();
        for (int s = 128; s > 0; s >>= 1) {
            if (tid < s) red[tid] += red[tid + s];
            __syncthreads();
        }
        int tot = red[0];
        __syncthreads();
        if (tot >= KK) thr = cand;
    }

    const int base = tid * (NN / 256);
    int lgt = 0, leq = 0;
#pragma unroll
    for (int j = 0; j < NN / 256; j++) {
        unsigned v = sv[base + j];
        lgt += (v > thr);
        leq += (v == thr);
    }
    red[tid] = lgt;
    cnts[tid] = leq;
    __syncthreads();
    if (tid == 0) {
        int a = 0;
        for (int i = 0; i < 256; i++) { gtoff[i] = a; a += red[i]; }
        tot_gt = a;
        a = 0;
        for (int i = 0; i < 256; i++) { eqoff[i] = a; a += cnts[i]; }
    }
    __syncthreads();

    const int ngt = tot_gt;
    int pgt = gtoff[tid];
    int peq = ngt + eqoff[tid];
    int*   ip = g_idx     + (size_t)be * KK;
    float* gp = g_gateval + (size_t)be * KK;
#pragma unroll
    for (int j = 0; j < NN / 256; j++) {
        unsigned v = sv[base + j];
        if (v > thr) {
            ip[pgt] = base + j;
            gp[pgt] = __uint_as_float(v);
            pgt++;
        } else if (v == thr) {
            if (peq < KK) {
                ip[peq] = base + j;
                gp[peq] = __uint_as_float(v);
            }
            peq++;
        }
    }
}

// ---------------- zero accumulator ------------------------------------------
__global__ void zero_kernel() {
    size_t i = ((size_t)blockIdx.x * blockDim.x + threadIdx.x) * 4;
    if (i < (size_t)BB * NN * DHH) {
        *(float4*)(g_xout + i) = make_float4(0.f, 0.f, 0.f, 0.f);
    }
}

// ---------------- fused gather -> FFN (tf32 mma) -> gated scatter ------------
// block = (token_tile 128, expert, batch), 512 threads, 16 warps (warp 32x32).
#define FS_X 132
#define FS_W 136
#define FFN_XS   (128 * FS_X)
#define FFN_WS   (128 * FS_W)
#define FFN_SMEM_FLOATS (2 * FFN_XS + FFN_WS + 256)
#define FFN_SMEM_BYTES (FFN_SMEM_FLOATS * 4)

__global__ __launch_bounds__(512, 1) void ffn_tf32_kernel(const float* __restrict__ w1r,
                                                          const float* __restrict__ w2r) {
    extern __shared__ float sm[];
    float* Xs = sm;
    float* Hs = sm + FFN_XS;
    float* Ws = sm + 2 * FFN_XS;
    int*   toks = (int*)(sm + 2 * FFN_XS + FFN_WS);
    float* Gs   = sm + 2 * FFN_XS + FFN_WS + 128;

    const int tile = blockIdx.x, e = blockIdx.y, b = blockIdx.z;
    const int tid = threadIdx.x;
    const int be = b * EE + e;
    const int* idxp = g_idx + (size_t)be * KK + tile * 128;
    const float* gvp = g_gateval + (size_t)be * KK + tile * 128;
    const float* w1e = w1r + (size_t)e * DHH * DFF;
    const float* w2e = w2r + (size_t)e * DFF * DHH;

    const int row = tid >> 2, seg = tid & 3;   // 512 threads: 128 rows x 4 segs of 32

    // prologue: issue async load of w1 chunk 0
    {
        float* wd = Ws + row * FS_W + seg * 32;
        const float* wsrc = w1e + (size_t)row * DFF + seg * 32;
#pragma unroll
        for (int j = 0; j < 32; j += 4) cp16(wd + j, wsrc + j);
    }
    CP_COMMIT;

    // gather X (convert to tf32 while staging)
    {
        const int tok = idxp[row];
        if (seg == 0) { toks[row] = tok; Gs[row] = gvp[row]; }
        const float* xr = g_x1 + ((size_t)b * NN + tok) * DHH + seg * 32;
        float* xd = Xs + row * FS_X + seg * 32;
#pragma unroll
        for (int j = 0; j < 32; j += 4) {
            float4 v = *(const float4*)(xr + j);
            xd[j]     = f_rna(v.x);
            xd[j + 1] = f_rna(v.y);
            xd[j + 2] = f_rna(v.z);
            xd[j + 3] = f_rna(v.w);
        }
    }

    const int warp = tid >> 5, lane = tid & 31;
    const int wm = (warp >> 2) * 32, wn = (warp & 3) * 32;
    const int ly = lane >> 2, lx = lane & 3;

    float yacc[2][4][4];
#pragma unroll
    for (int i = 0; i < 2; i++)
#pragma unroll
        for (int j = 0; j < 4; j++)
#pragma unroll
            for (int k = 0; k < 4; k++) yacc[i][j][k] = 0.f;

    for (int c = 0; c < 3; c++) {
        CP_WAIT0;
        __syncthreads();

        // H = Xs @ w1_chunk
        float h[2][4][4];
#pragma unroll
        for (int i = 0; i < 2; i++)
#pragma unroll
            for (int j = 0; j < 4; j++)
#pragma unroll
                for (int k = 0; k < 4; k++) h[i][j][k] = 0.f;

#pragma unroll 4
        for (int ks = 0; ks < 16; ks++) {
            const int k0 = ks * 8;
            uint32_t a[2][4], bf[4][2];
#pragma unroll
            for (int am = 0; am < 2; am++) {
                const int off = (wm + am * 16 + ly) * FS_X + k0 + lx;
                a[am][0] = __float_as_uint(Xs[off]);
                a[am][1] = __float_as_uint(Xs[off + 8 * FS_X]);
                a[am][2] = __float_as_uint(Xs[off + 4]);
                a[am][3] = __float_as_uint(Xs[off + 8 * FS_X + 4]);
            }
#pragma unroll
            for (int an = 0; an < 4; an++) {
                const int off = (k0 + lx) * FS_W + wn + an * 8 + ly;
                bf[an][0] = __float_as_uint(Ws[off]);
                bf[an][1] = __float_as_uint(Ws[off + 4 * FS_W]);
            }
#pragma unroll
            for (int am = 0; am < 2; am++)
#pragma unroll
                for (int an = 0; an < 4; an++) mma8(h[am][an], a[am], bf[an]);
        }
        __syncthreads();   // done reading w1 chunk

        // issue async load of w2 chunk c (overlaps silu below)
        {
            float* wd = Ws + row * FS_W + seg * 32;
            const float* wsrc = w2e + (size_t)(c * 128 + row) * DHH + seg * 32;
#pragma unroll
            for (int j = 0; j < 32; j += 4) cp16(wd + j, wsrc + j);
        }
        CP_COMMIT;

        // silu -> Hs (tf32-rounded)
#pragma unroll
        for (int am = 0; am < 2; am++) {
            const int r0 = wm + am * 16 + ly;
#pragma unroll
            for (int an = 0; an < 4; an++) {
                const int col = wn + an * 8 + 2 * lx;
                float v0 = h[am][an][0], v1 = h[am][an][1];
                float v2 = h[am][an][2], v3 = h[am][an][3];
                v0 = v0 / (1.f + expf(-v0));
                v1 = v1 / (1.f + expf(-v1));
                v2 = v2 / (1.f + expf(-v2));
                v3 = v3 / (1.f + expf(-v3));
                *(float2*)&Hs[r0 * FS_X + col]       = make_float2(f_rna(v0), f_rna(v1));
                *(float2*)&Hs[(r0 + 8) * FS_X + col] = make_float2(f_rna(v2), f_rna(v3));
            }
        }
        CP_WAIT0;
        __syncthreads();

        // Y += Hs @ w2_chunk
#pragma unroll 4
        for (int ks = 0; ks < 16; ks++) {
            const int k0 = ks * 8;
            uint32_t a[2][4], bf[4][2];
#pragma unroll
            for (int am = 0; am < 2; am++) {
                const int off = (wm + am * 16 + ly) * FS_X + k0 + lx;
                a[am][0] = __float_as_uint(Hs[off]);
                a[am][1] = __float_as_uint(Hs[off + 8 * FS_X]);
                a[am][2] = __float_as_uint(Hs[off + 4]);
                a[am][3] = __float_as_uint(Hs[off + 8 * FS_X + 4]);
            }
#pragma unroll
            for (int an = 0; an < 4; an++) {
                const int off = (k0 + lx) * FS_W + wn + an * 8 + ly;
                bf[an][0] = __float_as_uint(Ws[off]);
                bf[an][1] = __float_as_uint(Ws[off + 4 * FS_W]);
            }
#pragma unroll
            for (int am = 0; am < 2; am++)
#pragma unroll
                for (int an = 0; an < 4; an++) mma8(yacc[am][an], a[am], bf[an]);
        }
        __syncthreads();

        if (c < 2) {   // issue async load of next w1 chunk
            float* wd = Ws + row * FS_W + seg * 32;
            const float* wsrc = w1e + (size_t)row * DFF + (c + 1) * 128 + seg * 32;
#pragma unroll
            for (int j = 0; j < 32; j += 4) cp16(wd + j, wsrc + j);
            CP_COMMIT;
        }
    }

    // gated scatter-add
#pragma unroll
    for (int am = 0; am < 2; am++) {
        const int r0 = wm + am * 16 + ly;
        const int tok0 = toks[r0], tok1 = toks[r0 + 8];
        const float g0 = Gs[r0], g1 = Gs[r0 + 8];
        float* o0 = g_xout + ((size_t)b * NN + tok0) * DHH;
        float* o1 = g_xout + ((size_t)b * NN + tok1) * DHH;
#pragma unroll
        for (int an = 0; an < 4; an++) {
            const int col = wn + an * 8 + 2 * lx;
            atomicAdd(o0 + col,     yacc[am][an][0] * g0);
            atomicAdd(o0 + col + 1, yacc[am][an][1] * g0);
            atomicAdd(o1 + col,     yacc[am][an][2] * g1);
            atomicAdd(o1 + col + 1, yacc[am][an][3] * g1);
        }
    }
}

// ---------------- launch ----------------------------------------------------
extern "C" void kernel_launch(void* const* d_in, const int* in_sizes, int n_in,
                              void* d_out, int out_size) {
    const float* x      = (const float*)d_in[0];
    const float* choice = (const float*)d_in[1];
    const float* w1     = (const float*)d_in[2];
    const float* w2     = (const float*)d_in[3];
    const float* head   = (const float*)d_in[4];
    const float* merge  = (const float*)d_in[5];
    float* out = (float*)d_out;

    float *x1p, *xop, *w1r, *w2r;
    cudaGetSymbolAddress((void**)&x1p, g_x1);
    cudaGetSymbolAddress((void**)&xop, g_xout);
    cudaGetSymbolAddress((void**)&w1r, g_w1r);
    cudaGetSymbolAddress((void**)&w2r, g_w2r);

    cudaFuncSetAttribute(gemm1x_kernel, cudaFuncAttributeMaxDynamicSharedMemorySize,
                         MG_SMEM_BYTES);
    cudaFuncSetAttribute(ffn_tf32_kernel, cudaFuncAttributeMaxDynamicSharedMemorySize,
                         FFN_SMEM_BYTES);
    cudaFuncSetAttribute(logits_softmax_kernel, cudaFuncAttributeMaxDynamicSharedMemorySize,
                         LG_SMEM_BYTES);

    const size_t nW1 = (size_t)EE * DHH * DFF;  // 1179648

    // 0) fused gating matrix W = head_slices @ choice^T (exact fp32)
    choice_proj_kernel<<<DD, 144>>>(head, choice);

    // tf32 rounds for expert weights
    round_tf32_kernel<<<(unsigned)(nW1 / 1024), 256>>>(w1, w1r, nW1);
    round_tf32_kernel<<<(unsigned)(nW1 / 1024), 256>>>(w2, w2r, nW1);

    // 1) head projection (single-pass tf32; accuracy only needed for FFN path)
    dim3 gproj(DD / 128, (BB * SS) / 128);
    gemm1x_kernel<<<gproj, 256, MG_SMEM_BYTES>>>(x, head, x1p, BB * SS, DD, DD);

    // 2) exact-fp32 logits + softmax (independent of x1 accuracy)
    logits_softmax_kernel<<<(BB * SS) / 64, 384, LG_SMEM_BYTES>>>(x);

    // 3) per-(b,e) top-K
    topk_kernel<<<BB * EE, 256>>>();

    // 4) zero accumulator
    zero_kernel<<<(BB * NN * DHH) / (256 * 4), 256>>>();

    // 5) fused gather -> FFN (tf32 tensor) -> gated scatter
    dim3 gffn(KK / 128, EE, BB);
    ffn_tf32_kernel<<<gffn, 512, FFN_SMEM_BYTES>>>(w1r, w2r);

    // 6) merge projection (single-pass tf32)
    gemm1x_kernel<<<gproj, 256, MG_SMEM_BYTES>>>(xop, merge, out,
                                                 BB * SS, DD, DD);
}